// round 7
// baseline (speedup 1.0000x reference)
#include <cuda_runtime.h>
#include <cstdint>

#define D 1024
#define MAXR 16384
#define DD (D * D)
#define NRC 16                 // K chunks of 64 (int8)
#define STAGE 32768            // a1 8K | a2 8K | b1 8K | b2 8K (128 rows x 64B)
#define NSTG 4
#define SMEM_SZ (NSTG * STAGE) // 128 KB
#define INV254 (1.0f / 254.0f)

// ---------------- device scratch (allocation-free rule) ----------------
__device__ __align__(256) int8_t g_a1[MAXR * D], g_a2[MAXR * D];   // plane set 0
__device__ __align__(256) int8_t g_c1[MAXR * D], g_c2[MAXR * D];   // plane set 1
__device__ __align__(256) float  g_q[MAXR * D];                    // fp32 intermediate
__device__ __align__(256) int8_t g_w1[6 * DD], g_w2[6 * DD];       // weight planes
__device__ __align__(256) float  g_sa[MAXR];                       // row scales
__device__ __align__(256) float  g_sb[6 * D];                      // col scales

// smem swizzle: row stride 64B, 4 x 16B chunks per row (conflict-free ldmatrix)
__device__ __forceinline__ uint32_t soff(int row, int c) {
    return (uint32_t)(row * 64 + ((c ^ ((row >> 1) & 3)) << 4));
}

#define LDSM4(r0, r1, r2, r3, addr)                                               \
    asm volatile("ldmatrix.sync.aligned.m8n8.x4.shared.b16 {%0,%1,%2,%3}, [%4];"  \
                 : "=r"(r0), "=r"(r1), "=r"(r2), "=r"(r3) : "r"(addr))

#define IMMA(ac, af, bf)                                                          \
    asm volatile("mma.sync.aligned.m16n8k32.row.col.s32.s8.s8.s32 "               \
                 "{%0,%1,%2,%3}, {%4,%5,%6,%7}, {%8,%9}, {%0,%1,%2,%3};"          \
                 : "+r"((ac)[0]), "+r"((ac)[1]), "+r"((ac)[2]), "+r"((ac)[3])     \
                 : "r"((af)[0]), "r"((af)[1]), "r"((af)[2]), "r"((af)[3]),        \
                   "r"((bf)[0]), "r"((bf)[1]))

// ---------------- IMMA 2-plane int8 GEMM ----------------
// C[m,n] = sA_m*sB_n*(a1b1 + (a1b2 + a2b1)/254) + bias_n ; ACT 1 = silu.
template <int ACT>
__global__ void __launch_bounds__(256, 1)
gemm_imma(const int8_t* __restrict__ A1, const int8_t* __restrict__ A2,
          const int8_t* __restrict__ B1, const int8_t* __restrict__ B2,
          const float* __restrict__ sA, const float* __restrict__ sB,
          const float* __restrict__ bias, float* __restrict__ Cf) {
    extern __shared__ __align__(128) char smem[];
    const int tid = threadIdx.x, lane = tid & 31, wid = tid >> 5;
    const int bm = blockIdx.y * 128, bn = blockIdx.x * 128;
    const int wm = (wid >> 2) * 64, wn = (wid & 3) * 32;
    const uint32_t sb = (uint32_t)__cvta_generic_to_shared(smem);

    int acc1[4][4][4] = {};
    int acc2[4][4][4] = {};
    uint32_t a1f[4][4], a2f[4][4], b1f[4][2], b2f[4][2];

    auto stage_load = [&](int kt) {
        const uint32_t st = sb + (uint32_t)(kt & (NSTG - 1)) * STAGE;
        const int rk = kt * 64;
#pragma unroll
        for (int i = 0; i < 2; i++) {
            const int idx = tid + i * 256;
            const int row = idx >> 2, c = idx & 3;
            const uint32_t off = soff(row, c);
            const size_t ga = (size_t)(bm + row) * D + rk + c * 16;
            const size_t gb = (size_t)(bn + row) * D + rk + c * 16;
            asm volatile("cp.async.cg.shared.global [%0], [%1], 16;" :: "r"(st + off),         "l"(A1 + ga));
            asm volatile("cp.async.cg.shared.global [%0], [%1], 16;" :: "r"(st + 8192 + off),  "l"(A2 + ga));
            asm volatile("cp.async.cg.shared.global [%0], [%1], 16;" :: "r"(st + 16384 + off), "l"(B1 + gb));
            asm volatile("cp.async.cg.shared.global [%0], [%1], 16;" :: "r"(st + 24576 + off), "l"(B2 + gb));
        }
        asm volatile("cp.async.commit_group;" ::: "memory");
    };

    auto ldfrag = [&](uint32_t st, int kk) {
        const int ar = wm + (lane & 15);
        const int ac_ = kk * 2 + (lane >> 4);
        const int br = wn + ((lane >> 4) << 3) + (lane & 7);
        const int bc = kk * 2 + ((lane >> 3) & 1);
#pragma unroll
        for (int mf = 0; mf < 4; mf++)
            LDSM4(a1f[mf][0], a1f[mf][1], a1f[mf][2], a1f[mf][3],
                  st + soff(ar + mf * 16, ac_));
#pragma unroll
        for (int mf = 0; mf < 4; mf++)
            LDSM4(a2f[mf][0], a2f[mf][1], a2f[mf][2], a2f[mf][3],
                  st + 8192 + soff(ar + mf * 16, ac_));
#pragma unroll
        for (int g = 0; g < 2; g++) {
            uint32_t r0, r1, r2, r3;
            LDSM4(r0, r1, r2, r3, st + 16384 + soff(br + g * 16, bc));
            b1f[g * 2][0] = r0; b1f[g * 2][1] = r1;
            b1f[g * 2 + 1][0] = r2; b1f[g * 2 + 1][1] = r3;
        }
#pragma unroll
        for (int g = 0; g < 2; g++) {
            uint32_t r0, r1, r2, r3;
            LDSM4(r0, r1, r2, r3, st + 24576 + soff(br + g * 16, bc));
            b2f[g * 2][0] = r0; b2f[g * 2][1] = r1;
            b2f[g * 2 + 1][0] = r2; b2f[g * 2 + 1][1] = r3;
        }
    };

    auto mma_all = [&]() {
#pragma unroll
        for (int mf = 0; mf < 4; mf++)
#pragma unroll
            for (int nf = 0; nf < 4; nf++)
                IMMA(acc1[mf][nf], a1f[mf], b1f[nf]);
#pragma unroll
        for (int mf = 0; mf < 4; mf++)
#pragma unroll
            for (int nf = 0; nf < 4; nf++)
                IMMA(acc2[mf][nf], a1f[mf], b2f[nf]);
#pragma unroll
        for (int mf = 0; mf < 4; mf++)
#pragma unroll
            for (int nf = 0; nf < 4; nf++)
                IMMA(acc2[mf][nf], a2f[mf], b1f[nf]);
    };

    stage_load(0);
    stage_load(1);
    stage_load(2);

    for (int kt = 0; kt < NRC; kt++) {
        asm volatile("cp.async.wait_group 2;" ::: "memory");
        __syncthreads();
        const uint32_t st = sb + (uint32_t)(kt & (NSTG - 1)) * STAGE;
        ldfrag(st, 0);
        if (kt + 3 < NRC) stage_load(kt + 3);
        mma_all();
        ldfrag(st, 1);
        mma_all();
    }

    // ---- epilogue: dequant + bias (+silu), fp32 out ----
    float2 sb2[4];
    float2 bias2[4];
#pragma unroll
    for (int nf = 0; nf < 4; nf++) {
        const int n = bn + wn + nf * 8 + (lane & 3) * 2;
        sb2[nf] = *(const float2*)(sB + n);
        bias2[nf] = *(const float2*)(bias + n);
    }

#pragma unroll
    for (int mf = 0; mf < 4; mf++) {
#pragma unroll
        for (int rh = 0; rh < 2; rh++) {
            const int row = bm + wm + mf * 16 + (lane >> 2) + rh * 8;
            const float sar = sA[row];
#pragma unroll
            for (int nf = 0; nf < 4; nf++) {
                const int n = bn + wn + nf * 8 + (lane & 3) * 2;
                float c0 = (float)acc1[mf][nf][rh * 2 + 0] +
                           (float)acc2[mf][nf][rh * 2 + 0] * INV254;
                float c1 = (float)acc1[mf][nf][rh * 2 + 1] +
                           (float)acc2[mf][nf][rh * 2 + 1] * INV254;
                float v0 = sar * sb2[nf].x * c0 + bias2[nf].x;
                float v1 = sar * sb2[nf].y * c1 + bias2[nf].y;
                if (ACT == 1) {
                    v0 = v0 / (1.0f + __expf(-v0));
                    v1 = v1 / (1.0f + __expf(-v1));
                }
                *(float2*)(Cf + (size_t)row * D + n) = make_float2(v0, v1);
            }
        }
    }
}

// ---------------- block reduce helper (max) ----------------
__device__ __forceinline__ float block_max(float m, float* red, int tid) {
#pragma unroll
    for (int o = 16; o > 0; o >>= 1)
        m = fmaxf(m, __shfl_xor_sync(0xFFFFFFFFu, m, o));
    if ((tid & 31) == 0) red[tid >> 5] = m;
    __syncthreads();
    if (tid < 32) {
        float t = (tid < 8) ? red[tid] : 0.0f;
#pragma unroll
        for (int o = 4; o > 0; o >>= 1)
            t = fmaxf(t, __shfl_xor_sync(0xFFFFFFFFu, t, o));
        if (tid == 0) red[0] = t;
    }
    __syncthreads();
    return red[0];
}

__device__ __forceinline__ void quant4(float4 v, float inv, char4& q1, char4& q2) {
    float a0 = v.x * inv, a1 = v.y * inv, a2 = v.z * inv, a3 = v.w * inv;
    int i0 = __float2int_rn(a0), i1 = __float2int_rn(a1);
    int i2 = __float2int_rn(a2), i3 = __float2int_rn(a3);
    q1 = make_char4((char)i0, (char)i1, (char)i2, (char)i3);
    q2 = make_char4((char)__float2int_rn((a0 - i0) * 254.0f),
                    (char)__float2int_rn((a1 - i1) * 254.0f),
                    (char)__float2int_rn((a2 - i2) * 254.0f),
                    (char)__float2int_rn((a3 - i3) * 254.0f));
}

// ---------------- quantize rows (optionally after LayerNorm) ----------------
template <int LN>
__global__ void __launch_bounds__(256)
qrows(const float* __restrict__ in, int8_t* __restrict__ p1,
      int8_t* __restrict__ p2, float* __restrict__ sa) {
    __shared__ float red[8];
    const int row = blockIdx.x, tid = threadIdx.x;
    float4 v = *(const float4*)(in + (size_t)row * D + tid * 4);

    if (LN) {
        __shared__ float2 red2[8];
        float s = v.x + v.y + v.z + v.w;
        float ss = v.x * v.x + v.y * v.y + v.z * v.z + v.w * v.w;
#pragma unroll
        for (int o = 16; o > 0; o >>= 1) {
            s += __shfl_xor_sync(0xFFFFFFFFu, s, o);
            ss += __shfl_xor_sync(0xFFFFFFFFu, ss, o);
        }
        if ((tid & 31) == 0) red2[tid >> 5] = make_float2(s, ss);
        __syncthreads();
        if (tid < 32) {
            float2 r0 = (tid < 8) ? red2[tid] : make_float2(0.f, 0.f);
            s = r0.x; ss = r0.y;
#pragma unroll
            for (int o = 4; o > 0; o >>= 1) {
                s += __shfl_xor_sync(0xFFFFFFFFu, s, o);
                ss += __shfl_xor_sync(0xFFFFFFFFu, ss, o);
            }
            if (tid == 0) red2[0] = make_float2(s, ss);
        }
        __syncthreads();
        const float mu = red2[0].x * (1.0f / D);
        const float var = red2[0].y * (1.0f / D) - mu * mu;
        const float r = rsqrtf(var + 1e-5f);
        v = make_float4((v.x - mu) * r, (v.y - mu) * r, (v.z - mu) * r, (v.w - mu) * r);
        __syncthreads();
    }

    float m = fmaxf(fmaxf(fabsf(v.x), fabsf(v.y)), fmaxf(fabsf(v.z), fabsf(v.w)));
    m = block_max(m, red, tid);
    m = fmaxf(m, 1e-30f);
    const float inv = 127.0f / m;

    char4 q1, q2;
    quant4(v, inv, q1, q2);
    *(char4*)(p1 + (size_t)row * D + tid * 4) = q1;
    *(char4*)(p2 + (size_t)row * D + tid * 4) = q2;
    if (tid == 0) sa[row] = m * (1.0f / 127.0f);
}

// ---------------- weight prep: W[k][n] -> planes[n][k] + per-col scale ----------------
__global__ void __launch_bounds__(256)
wprep(const float* __restrict__ W, int8_t* __restrict__ b1,
      int8_t* __restrict__ b2, float* __restrict__ sB) {
    __shared__ float red[8];
    const int n = blockIdx.x, tid = threadIdx.x;
    float v[4];
#pragma unroll
    for (int i = 0; i < 4; i++) v[i] = W[(size_t)(tid + i * 256) * D + n];
    float m = 0.0f;
#pragma unroll
    for (int i = 0; i < 4; i++) m = fmaxf(m, fabsf(v[i]));
    m = block_max(m, red, tid);
    m = fmaxf(m, 1e-30f);
    const float inv = 127.0f / m;
#pragma unroll
    for (int i = 0; i < 4; i++) {
        float a = v[i] * inv;
        int i1 = __float2int_rn(a);
        int i2 = __float2int_rn((a - i1) * 254.0f);
        b1[(size_t)n * D + tid + i * 256] = (int8_t)i1;
        b2[(size_t)n * D + tid + i * 256] = (int8_t)i2;
    }
    if (tid == 0) sB[n] = m * (1.0f / 127.0f);
}

// ---------------- launch ----------------
extern "C" void kernel_launch(void* const* d_in, const int* in_sizes, int n_in,
                              void* d_out, int out_size) {
    const float* x     = (const float*)d_in[0];
    const float* wq    = (const float*)d_in[1];
    const float* bq    = (const float*)d_in[2];
    const float* mlp_w = (const float*)d_in[3];
    const float* mlp_b = (const float*)d_in[4];
    const float* w_out = (const float*)d_in[5];
    const float* b_out = (const float*)d_in[6];
    float* out = (float*)d_out;
    const int M = in_sizes[0] / D;   // 16384

    int8_t *a1, *a2, *c1, *c2, *w1, *w2;
    float *q, *sa, *sbv;
    cudaGetSymbolAddress((void**)&a1, g_a1);
    cudaGetSymbolAddress((void**)&a2, g_a2);
    cudaGetSymbolAddress((void**)&c1, g_c1);
    cudaGetSymbolAddress((void**)&c2, g_c2);
    cudaGetSymbolAddress((void**)&w1, g_w1);
    cudaGetSymbolAddress((void**)&w2, g_w2);
    cudaGetSymbolAddress((void**)&q, g_q);
    cudaGetSymbolAddress((void**)&sa, g_sa);
    cudaGetSymbolAddress((void**)&sbv, g_sb);

    cudaFuncSetAttribute(gemm_imma<0>, cudaFuncAttributeMaxDynamicSharedMemorySize, SMEM_SZ);
    cudaFuncSetAttribute(gemm_imma<1>, cudaFuncAttributeMaxDynamicSharedMemorySize, SMEM_SZ);

    // weight prep (6 weights): wq, mlp_w[0..3], w_out
    wprep<<<D, 256>>>(wq, w1, w2, sbv);
    for (int i = 0; i < 4; i++)
        wprep<<<D, 256>>>(mlp_w + (size_t)i * DD, w1 + (size_t)(1 + i) * DD,
                          w2 + (size_t)(1 + i) * DD, sbv + (1 + i) * D);
    wprep<<<D, 256>>>(w_out, w1 + 5ull * DD, w2 + 5ull * DD, sbv + 5 * D);

    // quantize x
    qrows<0><<<M, 256>>>(x, a1, a2, sa);

    dim3 gg(D / 128, M / 128), bb(256);
    // q = x @ wq + bq
    gemm_imma<0><<<gg, bb, SMEM_SZ>>>(a1, a2, w1, w2, sa, sbv, bq, q);
    // q_norm = LN(q), quantize
    qrows<1><<<M, 256>>>(q, c1, c2, sa);
    // MLP layer 0 (+silu)
    gemm_imma<1><<<gg, bb, SMEM_SZ>>>(c1, c2, w1 + 1ull * DD, w2 + 1ull * DD,
                                      sa, sbv + 1 * D, mlp_b + 0 * D, q);
    qrows<0><<<M, 256>>>(q, a1, a2, sa);
    // MLP layer 1 (+silu)
    gemm_imma<1><<<gg, bb, SMEM_SZ>>>(a1, a2, w1 + 2ull * DD, w2 + 2ull * DD,
                                      sa, sbv + 2 * D, mlp_b + 1 * D, q);
    qrows<0><<<M, 256>>>(q, c1, c2, sa);
    // MLP layer 2 (+silu)
    gemm_imma<1><<<gg, bb, SMEM_SZ>>>(c1, c2, w1 + 3ull * DD, w2 + 3ull * DD,
                                      sa, sbv + 3 * D, mlp_b + 2 * D, q);
    qrows<0><<<M, 256>>>(q, a1, a2, sa);
    // MLP layer 3 (no act)
    gemm_imma<0><<<gg, bb, SMEM_SZ>>>(a1, a2, w1 + 4ull * DD, w2 + 4ull * DD,
                                      sa, sbv + 4 * D, mlp_b + 3 * D, q);
    qrows<0><<<M, 256>>>(q, c1, c2, sa);
    // out = h @ w_out + b_out (straight-through adds 0 in forward)
    gemm_imma<0><<<gg, bb, SMEM_SZ>>>(c1, c2, w1 + 5ull * DD, w2 + 5ull * DD,
                                      sa, sbv + 5 * D, b_out, out);
}

// round 8
// speedup vs baseline: 3.7738x; 3.7738x over previous
#include <cuda_runtime.h>
#include <cuda_fp16.h>
#include <cstdint>

#define D 1024
#define MAXR 16384
#define DD (D * D)
#define NRC 32                 // K chunks of 32
#define STAGE 32768            // A1 8K | A2 8K | B1 8K | B2 8K
#define NSTG 4
#define SMEM_SZ (NSTG * STAGE) // 128 KB
#define SRES 64.0f
#define INV_S (1.0f / 64.0f)

// ---------------- device scratch (allocation-free rule) ----------------
__device__ __align__(256) __half g_a1[MAXR * D], g_a2[MAXR * D];
__device__ __align__(256) __half g_c1[MAXR * D], g_c2[MAXR * D];
__device__ __align__(256) float  g_q[MAXR * D];
__device__ __align__(256) __half g_w1[6 * DD], g_w2[6 * DD];

// scaled-residual fp16 pair: v ~= P1 + (P2 - P1)/64
__device__ __forceinline__ void splitp(float a, float b, uint32_t& p1, uint32_t& p2) {
    __half2 h1 = __floats2half2_rn(a, b);
    float2 f1 = __half22float2(h1);
    __half2 h2 = __floats2half2_rn(f1.x + SRES * (a - f1.x), f1.y + SRES * (b - f1.y));
    p1 = *reinterpret_cast<uint32_t*>(&h1);
    p2 = *reinterpret_cast<uint32_t*>(&h2);
}

// smem swizzle: row stride 64B, 4 x 16B chunks per row (conflict-free ldmatrix)
__device__ __forceinline__ uint32_t soff(int row, int c) {
    return (uint32_t)(row * 64 + ((c ^ ((row >> 1) & 3)) << 4));
}

#define LDSM4(r0, r1, r2, r3, addr)                                               \
    asm volatile("ldmatrix.sync.aligned.m8n8.x4.shared.b16 {%0,%1,%2,%3}, [%4];"  \
                 : "=r"(r0), "=r"(r1), "=r"(r2), "=r"(r3) : "r"(addr))

#define MMAF16(ac, af, bf)                                                        \
    asm volatile("mma.sync.aligned.m16n8k16.row.col.f32.f16.f16.f32 "             \
                 "{%0,%1,%2,%3}, {%4,%5,%6,%7}, {%8,%9}, {%0,%1,%2,%3};"          \
                 : "+f"((ac)[0]), "+f"((ac)[1]), "+f"((ac)[2]), "+f"((ac)[3])     \
                 : "r"((af)[0]), "r"((af)[1]), "r"((af)[2]), "r"((af)[3]),        \
                   "r"((bf)[0]), "r"((bf)[1]))

// ---------------- HMMA 2-product scaled-residual GEMM ----------------
// C = P1 + (P2 - P1)/64 + bias ; ACT 1 = silu.
// WMODE: 0 = write fp16 plane pair, 1 = write fp32.
template <int ACT, int WMODE>
__global__ void __launch_bounds__(256, 1)
gemm_hmma(const __half* __restrict__ A1, const __half* __restrict__ A2,
          const __half* __restrict__ B1, const __half* __restrict__ B2,
          const float* __restrict__ bias,
          __half* __restrict__ C1, __half* __restrict__ C2,
          float* __restrict__ Cf) {
    extern __shared__ __align__(128) char smem[];
    const int tid = threadIdx.x, lane = tid & 31, wid = tid >> 5;
    const int bm = blockIdx.y * 128, bn = blockIdx.x * 128;
    const int wm = (wid >> 2) * 64, wn = (wid & 3) * 32;
    const uint32_t sb = (uint32_t)__cvta_generic_to_shared(smem);

    float acc1[4][4][4] = {};
    float acc2[4][4][4] = {};
    uint32_t a1f[4][4], a2f[4][4], b1f[4][2], b2f[4][2];

    auto stage_load = [&](int kt) {
        const uint32_t st = sb + (uint32_t)(kt & (NSTG - 1)) * STAGE;
        const int rk = kt * 32;
#pragma unroll
        for (int i = 0; i < 2; i++) {
            const int idx = tid + i * 256;
            const int row = idx >> 2, c = idx & 3;
            const uint32_t off = soff(row, c);
            const size_t ga = (size_t)(bm + row) * D + rk + c * 8;
            const size_t gb = (size_t)(bn + row) * D + rk + c * 8;
            asm volatile("cp.async.cg.shared.global [%0], [%1], 16;" :: "r"(st + off),         "l"(A1 + ga));
            asm volatile("cp.async.cg.shared.global [%0], [%1], 16;" :: "r"(st + 8192 + off),  "l"(A2 + ga));
            asm volatile("cp.async.cg.shared.global [%0], [%1], 16;" :: "r"(st + 16384 + off), "l"(B1 + gb));
            asm volatile("cp.async.cg.shared.global [%0], [%1], 16;" :: "r"(st + 24576 + off), "l"(B2 + gb));
        }
        asm volatile("cp.async.commit_group;" ::: "memory");
    };

    auto ld1 = [&](uint32_t st, int kk) {   // A1 + B1 fragments
        const int ar = wm + (lane & 15);
        const int ac_ = kk * 2 + (lane >> 4);
        const int br = wn + ((lane >> 4) << 3) + (lane & 7);
        const int bc = kk * 2 + ((lane >> 3) & 1);
#pragma unroll
        for (int mf = 0; mf < 4; mf++)
            LDSM4(a1f[mf][0], a1f[mf][1], a1f[mf][2], a1f[mf][3],
                  st + soff(ar + mf * 16, ac_));
#pragma unroll
        for (int g = 0; g < 2; g++) {
            uint32_t r0, r1, r2, r3;
            LDSM4(r0, r1, r2, r3, st + 16384 + soff(br + g * 16, bc));
            b1f[g * 2][0] = r0; b1f[g * 2][1] = r1;
            b1f[g * 2 + 1][0] = r2; b1f[g * 2 + 1][1] = r3;
        }
    };
    auto ld2 = [&](uint32_t st, int kk) {   // A2 + B2 fragments
        const int ar = wm + (lane & 15);
        const int ac_ = kk * 2 + (lane >> 4);
        const int br = wn + ((lane >> 4) << 3) + (lane & 7);
        const int bc = kk * 2 + ((lane >> 3) & 1);
#pragma unroll
        for (int mf = 0; mf < 4; mf++)
            LDSM4(a2f[mf][0], a2f[mf][1], a2f[mf][2], a2f[mf][3],
                  st + 8192 + soff(ar + mf * 16, ac_));
#pragma unroll
        for (int g = 0; g < 2; g++) {
            uint32_t r0, r1, r2, r3;
            LDSM4(r0, r1, r2, r3, st + 24576 + soff(br + g * 16, bc));
            b2f[g * 2][0] = r0; b2f[g * 2][1] = r1;
            b2f[g * 2 + 1][0] = r2; b2f[g * 2 + 1][1] = r3;
        }
    };

    auto mmaP1 = [&]() {
#pragma unroll
        for (int mf = 0; mf < 4; mf++)
#pragma unroll
            for (int nf = 0; nf < 4; nf++)
                MMAF16(acc1[mf][nf], a1f[mf], b1f[nf]);
    };
    auto mmaP2 = [&]() {
#pragma unroll
        for (int mf = 0; mf < 4; mf++)
#pragma unroll
            for (int nf = 0; nf < 4; nf++)
                MMAF16(acc2[mf][nf], a2f[mf], b2f[nf]);
    };

    stage_load(0);
    stage_load(1);
    stage_load(2);
    asm volatile("cp.async.wait_group 2;" ::: "memory");
    __syncthreads();
    ld1(sb, 0);

    for (int kt = 0; kt < NRC; kt++) {
        const uint32_t st = sb + (uint32_t)(kt & (NSTG - 1)) * STAGE;
        ld2(st, 0);
        mmaP1();                       // P1 kh0 hides ld2 latency
        if (kt + 3 < NRC) stage_load(kt + 3);
        else asm volatile("cp.async.commit_group;" ::: "memory");
        ld1(st, 1);
        mmaP2();                       // P2 kh0 hides ld1(kh1)
        ld2(st, 1);
        mmaP1();                       // P1 kh1 hides ld2(kh1)
        asm volatile("cp.async.wait_group 2;" ::: "memory");
        __syncthreads();
        if (kt + 1 < NRC)
            ld1(sb + (uint32_t)((kt + 1) & (NSTG - 1)) * STAGE, 0);
        mmaP2();                       // P2 kh1 hides ld1(next chunk)
    }

    // ---- epilogue: recombine + bias (+silu), store ----
    float2 bias2[4];
#pragma unroll
    for (int nf = 0; nf < 4; nf++)
        bias2[nf] = __ldg((const float2*)(bias + bn + wn + nf * 8 + (lane & 3) * 2));

#pragma unroll
    for (int mf = 0; mf < 4; mf++) {
#pragma unroll
        for (int rh = 0; rh < 2; rh++) {
            const int row = bm + wm + mf * 16 + (lane >> 2) + rh * 8;
#pragma unroll
            for (int nf = 0; nf < 4; nf++) {
                const int n = bn + wn + nf * 8 + (lane & 3) * 2;
                float p10 = acc1[mf][nf][rh * 2 + 0], p20 = acc2[mf][nf][rh * 2 + 0];
                float p11 = acc1[mf][nf][rh * 2 + 1], p21 = acc2[mf][nf][rh * 2 + 1];
                float v0 = p10 + (p20 - p10) * INV_S + bias2[nf].x;
                float v1 = p11 + (p21 - p11) * INV_S + bias2[nf].y;
                if (ACT == 1) {
                    v0 = v0 / (1.0f + __expf(-v0));
                    v1 = v1 / (1.0f + __expf(-v1));
                }
                if (WMODE == 0) {
                    uint32_t q1, q2;
                    splitp(v0, v1, q1, q2);
                    *(uint32_t*)(C1 + (size_t)row * D + n) = q1;
                    *(uint32_t*)(C2 + (size_t)row * D + n) = q2;
                } else {
                    *(float2*)(Cf + (size_t)row * D + n) = make_float2(v0, v1);
                }
            }
        }
    }
}

// ---------------- aux kernels ----------------
__global__ void __launch_bounds__(256) xsplit(const float2* __restrict__ x,
                                              uint32_t* __restrict__ p1,
                                              uint32_t* __restrict__ p2) {
    size_t i = (size_t)blockIdx.x * 256 + threadIdx.x;
    float2 v = x[i];
    uint32_t a, b;
    splitp(v.x, v.y, a, b);
    p1[i] = a; p2[i] = b;
}

// all 6 weights: W[k][n] -> T[n][k] plane pair  (z selects weight)
__global__ void __launch_bounds__(256)
wsplit_all(const float* __restrict__ wq, const float* __restrict__ mlp_w,
           const float* __restrict__ w_out,
           __half* __restrict__ T1, __half* __restrict__ T2) {
    __shared__ float t[32][33];
    const int z = blockIdx.z;
    const float* W = (z == 0) ? wq : (z <= 4 ? mlp_w + (size_t)(z - 1) * DD : w_out);
    __half* t1 = T1 + (size_t)z * DD;
    __half* t2 = T2 + (size_t)z * DD;
    const int bx = blockIdx.x * 32, by = blockIdx.y * 32;
    const int tx = threadIdx.x, ty = threadIdx.y;
#pragma unroll
    for (int i = 0; i < 32; i += 8) t[ty + i][tx] = W[(size_t)(by + ty + i) * D + bx + tx];
    __syncthreads();
#pragma unroll
    for (int i = 0; i < 32; i += 8) {
        float v = t[tx][ty + i];
        __half h1 = __float2half_rn(v);
        float f1 = __half2float(h1);
        size_t o = (size_t)(bx + ty + i) * D + by + tx;
        t1[o] = h1;
        t2[o] = __float2half_rn(f1 + SRES * (v - f1));
    }
}

// LayerNorm (D=1024, eps=1e-5, no affine) fused with plane-pair output
__global__ void __launch_bounds__(256) ln_split(const float* __restrict__ in,
                                                uint32_t* __restrict__ p1,
                                                uint32_t* __restrict__ p2) {
    __shared__ float2 red[8];
    const int row = blockIdx.x;
    const int tid = threadIdx.x;
    const float4 v = *(const float4*)(in + (size_t)row * D + tid * 4);
    float s = v.x + v.y + v.z + v.w;
    float ss = v.x * v.x + v.y * v.y + v.z * v.z + v.w * v.w;
#pragma unroll
    for (int o = 16; o > 0; o >>= 1) {
        s += __shfl_xor_sync(0xFFFFFFFFu, s, o);
        ss += __shfl_xor_sync(0xFFFFFFFFu, ss, o);
    }
    if ((tid & 31) == 0) red[tid >> 5] = make_float2(s, ss);
    __syncthreads();
    if (tid < 32) {
        float2 r0 = (tid < 8) ? red[tid] : make_float2(0.f, 0.f);
        s = r0.x; ss = r0.y;
#pragma unroll
        for (int o = 4; o > 0; o >>= 1) {
            s += __shfl_xor_sync(0xFFFFFFFFu, s, o);
            ss += __shfl_xor_sync(0xFFFFFFFFu, ss, o);
        }
        if (tid == 0) red[0] = make_float2(s, ss);
    }
    __syncthreads();
    const float mu = red[0].x * (1.0f / D);
    const float var = red[0].y * (1.0f / D) - mu * mu;
    const float r = rsqrtf(var + 1e-5f);
    uint2 h1, h2;
    splitp((v.x - mu) * r, (v.y - mu) * r, h1.x, h2.x);
    splitp((v.z - mu) * r, (v.w - mu) * r, h1.y, h2.y);
    *(uint2*)&p1[(size_t)row * (D / 2) + tid * 2] = h1;
    *(uint2*)&p2[(size_t)row * (D / 2) + tid * 2] = h2;
}

// ---------------- launch ----------------
extern "C" void kernel_launch(void* const* d_in, const int* in_sizes, int n_in,
                              void* d_out, int out_size) {
    const float* x     = (const float*)d_in[0];
    const float* wq    = (const float*)d_in[1];
    const float* bq    = (const float*)d_in[2];
    const float* mlp_w = (const float*)d_in[3];
    const float* mlp_b = (const float*)d_in[4];
    const float* w_out = (const float*)d_in[5];
    const float* b_out = (const float*)d_in[6];
    float* out = (float*)d_out;
    const int M = in_sizes[0] / D;   // 16384

    __half *a1, *a2, *c1, *c2, *w1, *w2;
    float* q;
    cudaGetSymbolAddress((void**)&a1, g_a1);
    cudaGetSymbolAddress((void**)&a2, g_a2);
    cudaGetSymbolAddress((void**)&c1, g_c1);
    cudaGetSymbolAddress((void**)&c2, g_c2);
    cudaGetSymbolAddress((void**)&w1, g_w1);
    cudaGetSymbolAddress((void**)&w2, g_w2);
    cudaGetSymbolAddress((void**)&q, g_q);

    cudaFuncSetAttribute(gemm_hmma<0, 1>, cudaFuncAttributeMaxDynamicSharedMemorySize, SMEM_SZ);
    cudaFuncSetAttribute(gemm_hmma<1, 0>, cudaFuncAttributeMaxDynamicSharedMemorySize, SMEM_SZ);
    cudaFuncSetAttribute(gemm_hmma<0, 0>, cudaFuncAttributeMaxDynamicSharedMemorySize, SMEM_SZ);

    dim3 wg(D / 32, D / 32, 6), wb(32, 8);
    wsplit_all<<<wg, wb>>>(wq, mlp_w, w_out, w1, w2);

    xsplit<<<(M * D) / 512, 256>>>((const float2*)x, (uint32_t*)a1, (uint32_t*)a2);

    dim3 gg(D / 128, M / 128), bb(256);
    // q = x @ wq + bq (fp32 out)
    gemm_hmma<0, 1><<<gg, bb, SMEM_SZ>>>(a1, a2, w1, w2, bq, nullptr, nullptr, q);
    // q_norm = LN(q) -> plane pair
    ln_split<<<M, 256>>>(q, (uint32_t*)c1, (uint32_t*)c2);
    // memory MLP: 3x (GEMM+SiLU), final GEMM no act
    gemm_hmma<1, 0><<<gg, bb, SMEM_SZ>>>(c1, c2, w1 + 1ull * DD, w2 + 1ull * DD, mlp_b + 0 * D, a1, a2, nullptr);
    gemm_hmma<1, 0><<<gg, bb, SMEM_SZ>>>(a1, a2, w1 + 2ull * DD, w2 + 2ull * DD, mlp_b + 1 * D, c1, c2, nullptr);
    gemm_hmma<1, 0><<<gg, bb, SMEM_SZ>>>(c1, c2, w1 + 3ull * DD, w2 + 3ull * DD, mlp_b + 2 * D, a1, a2, nullptr);
    gemm_hmma<0, 0><<<gg, bb, SMEM_SZ>>>(a1, a2, w1 + 4ull * DD, w2 + 4ull * DD, mlp_b + 3 * D, c1, c2, nullptr);
    // out = h @ w_out + b_out (straight-through term is 0 in forward)
    gemm_hmma<0, 1><<<gg, bb, SMEM_SZ>>>(c1, c2, w1 + 5ull * DD, w2 + 5ull * DD, b_out, nullptr, nullptr, out);
}

// round 9
// speedup vs baseline: 4.1855x; 1.1091x over previous
#include <cuda_runtime.h>
#include <cuda_fp16.h>
#include <cstdint>

#define D 1024
#define MAXR 16384
#define DD (D * D)
#define NRC 32                 // K chunks of 32
#define STAGE 32768            // A1 8K | A2 8K | B1 8K | B2 8K
#define NSTG 2
#define SMEM_SZ (NSTG * STAGE) // 64 KB -> 2 CTAs/SM
#define SRES 64.0f

// ---------------- device scratch (allocation-free rule) ----------------
__device__ __align__(256) __half g_a1[MAXR * D], g_a2[MAXR * D];
__device__ __align__(256) __half g_c1[MAXR * D], g_c2[MAXR * D];
__device__ __align__(256) float  g_q[MAXR * D];
__device__ __align__(256) __half g_w1[6 * DD], g_w2[6 * DD];

// A-side scaled-residual pair: a ~= A1 (+ residual encoded in A2 = A1 + 64(a-A1))
__device__ __forceinline__ void splitp(float a, float b, uint32_t& p1, uint32_t& p2) {
    __half2 h1 = __floats2half2_rn(a, b);
    float2 f1 = __half22float2(h1);
    __half2 h2 = __floats2half2_rn(f1.x + SRES * (a - f1.x), f1.y + SRES * (b - f1.y));
    p1 = *reinterpret_cast<uint32_t*>(&h1);
    p2 = *reinterpret_cast<uint32_t*>(&h2);
}

// smem swizzle: row stride 64B, 4 x 16B chunks per row (conflict-free ldmatrix)
__device__ __forceinline__ uint32_t soff(int row, int c) {
    return (uint32_t)(row * 64 + ((c ^ ((row >> 1) & 3)) << 4));
}

#define LDSM4(r0, r1, r2, r3, addr)                                               \
    asm volatile("ldmatrix.sync.aligned.m8n8.x4.shared.b16 {%0,%1,%2,%3}, [%4];"  \
                 : "=r"(r0), "=r"(r1), "=r"(r2), "=r"(r3) : "r"(addr))

#define MMAF16(ac, af, bf)                                                        \
    asm volatile("mma.sync.aligned.m16n8k16.row.col.f32.f16.f16.f32 "             \
                 "{%0,%1,%2,%3}, {%4,%5,%6,%7}, {%8,%9}, {%0,%1,%2,%3};"          \
                 : "+f"((ac)[0]), "+f"((ac)[1]), "+f"((ac)[2]), "+f"((ac)[3])     \
                 : "r"((af)[0]), "r"((af)[1]), "r"((af)[2]), "r"((af)[3]),        \
                   "r"((bf)[0]), "r"((bf)[1]))

// ---------------- HMMA single-accumulator 2-plane GEMM ----------------
// C = Sum A1*B1s + Sum A2*B2s + bias  (weights carry recombination scales)
// ACT 1 = silu. WMODE: 0 = write fp16 plane pair, 1 = write fp32.
template <int ACT, int WMODE>
__global__ void __launch_bounds__(256, 2)
gemm_hmma(const __half* __restrict__ A1, const __half* __restrict__ A2,
          const __half* __restrict__ B1, const __half* __restrict__ B2,
          const float* __restrict__ bias,
          __half* __restrict__ C1, __half* __restrict__ C2,
          float* __restrict__ Cf) {
    extern __shared__ __align__(128) char smem[];
    const int tid = threadIdx.x, lane = tid & 31, wid = tid >> 5;
    const int bm = blockIdx.y * 128, bn = blockIdx.x * 128;
    const int wm = (wid >> 2) * 64, wn = (wid & 3) * 32;
    const uint32_t sb = (uint32_t)__cvta_generic_to_shared(smem);

    float acc[4][4][4] = {};
    uint32_t a1f[4][4], a2f[4][4], b1f[4][2], b2f[4][2];

    auto stage_load = [&](int kt) {
        const uint32_t st = sb + (uint32_t)(kt & (NSTG - 1)) * STAGE;
        const int rk = kt * 32;
#pragma unroll
        for (int i = 0; i < 2; i++) {
            const int idx = tid + i * 256;
            const int row = idx >> 2, c = idx & 3;
            const uint32_t off = soff(row, c);
            const size_t ga = (size_t)(bm + row) * D + rk + c * 8;
            const size_t gb = (size_t)(bn + row) * D + rk + c * 8;
            asm volatile("cp.async.cg.shared.global [%0], [%1], 16;" :: "r"(st + off),         "l"(A1 + ga));
            asm volatile("cp.async.cg.shared.global [%0], [%1], 16;" :: "r"(st + 8192 + off),  "l"(A2 + ga));
            asm volatile("cp.async.cg.shared.global [%0], [%1], 16;" :: "r"(st + 16384 + off), "l"(B1 + gb));
            asm volatile("cp.async.cg.shared.global [%0], [%1], 16;" :: "r"(st + 24576 + off), "l"(B2 + gb));
        }
        asm volatile("cp.async.commit_group;" ::: "memory");
    };

    auto ld1 = [&](uint32_t st, int kk) {   // A1 + B1s fragments
        const int ar = wm + (lane & 15);
        const int ac_ = kk * 2 + (lane >> 4);
        const int br = wn + ((lane >> 4) << 3) + (lane & 7);
        const int bc = kk * 2 + ((lane >> 3) & 1);
#pragma unroll
        for (int mf = 0; mf < 4; mf++)
            LDSM4(a1f[mf][0], a1f[mf][1], a1f[mf][2], a1f[mf][3],
                  st + soff(ar + mf * 16, ac_));
#pragma unroll
        for (int g = 0; g < 2; g++) {
            uint32_t r0, r1, r2, r3;
            LDSM4(r0, r1, r2, r3, st + 16384 + soff(br + g * 16, bc));
            b1f[g * 2][0] = r0; b1f[g * 2][1] = r1;
            b1f[g * 2 + 1][0] = r2; b1f[g * 2 + 1][1] = r3;
        }
    };
    auto ld2 = [&](uint32_t st, int kk) {   // A2 + B2s fragments
        const int ar = wm + (lane & 15);
        const int ac_ = kk * 2 + (lane >> 4);
        const int br = wn + ((lane >> 4) << 3) + (lane & 7);
        const int bc = kk * 2 + ((lane >> 3) & 1);
#pragma unroll
        for (int mf = 0; mf < 4; mf++)
            LDSM4(a2f[mf][0], a2f[mf][1], a2f[mf][2], a2f[mf][3],
                  st + 8192 + soff(ar + mf * 16, ac_));
#pragma unroll
        for (int g = 0; g < 2; g++) {
            uint32_t r0, r1, r2, r3;
            LDSM4(r0, r1, r2, r3, st + 24576 + soff(br + g * 16, bc));
            b2f[g * 2][0] = r0; b2f[g * 2][1] = r1;
            b2f[g * 2 + 1][0] = r2; b2f[g * 2 + 1][1] = r3;
        }
    };

    auto mma1 = [&]() {
#pragma unroll
        for (int mf = 0; mf < 4; mf++)
#pragma unroll
            for (int nf = 0; nf < 4; nf++)
                MMAF16(acc[mf][nf], a1f[mf], b1f[nf]);
    };
    auto mma2 = [&]() {
#pragma unroll
        for (int mf = 0; mf < 4; mf++)
#pragma unroll
            for (int nf = 0; nf < 4; nf++)
                MMAF16(acc[mf][nf], a2f[mf], b2f[nf]);
    };

    stage_load(0);
    asm volatile("cp.async.wait_group 0;" ::: "memory");
    __syncthreads();
    ld1(sb, 0);

    for (int kt = 0; kt < NRC; kt++) {
        const uint32_t st = sb + (uint32_t)(kt & (NSTG - 1)) * STAGE;
        ld2(st, 0);
        if (kt + 1 < NRC) stage_load(kt + 1);
        mma1();                        // product1 kh0 (hides ld2)
        ld1(st, 1);
        mma2();                        // product2 kh0 (hides ld1 kh1)
        ld2(st, 1);
        mma1();                        // product1 kh1 (hides ld2 kh1)
        if (kt + 1 < NRC) {
            asm volatile("cp.async.wait_group 0;" ::: "memory");
            __syncthreads();
            ld1(sb + (uint32_t)((kt + 1) & (NSTG - 1)) * STAGE, 0);
        }
        mma2();                        // product2 kh1 (hides next ld1)
    }

    // ---- epilogue: bias (+silu), store ----
    float2 bias2[4];
#pragma unroll
    for (int nf = 0; nf < 4; nf++)
        bias2[nf] = __ldg((const float2*)(bias + bn + wn + nf * 8 + (lane & 3) * 2));

#pragma unroll
    for (int mf = 0; mf < 4; mf++) {
#pragma unroll
        for (int rh = 0; rh < 2; rh++) {
            const int row = bm + wm + mf * 16 + (lane >> 2) + rh * 8;
#pragma unroll
            for (int nf = 0; nf < 4; nf++) {
                const int n = bn + wn + nf * 8 + (lane & 3) * 2;
                float v0 = acc[mf][nf][rh * 2 + 0] + bias2[nf].x;
                float v1 = acc[mf][nf][rh * 2 + 1] + bias2[nf].y;
                if (ACT == 1) {
                    v0 = v0 / (1.0f + __expf(-v0));
                    v1 = v1 / (1.0f + __expf(-v1));
                }
                if (WMODE == 0) {
                    uint32_t q1, q2;
                    splitp(v0, v1, q1, q2);
                    *(uint32_t*)(C1 + (size_t)row * D + n) = q1;
                    *(uint32_t*)(C2 + (size_t)row * D + n) = q2;
                } else {
                    *(float2*)(Cf + (size_t)row * D + n) = make_float2(v0, v1);
                }
            }
        }
    }
}

// ---------------- aux kernels ----------------
__global__ void __launch_bounds__(256) xsplit(const float2* __restrict__ x,
                                              uint32_t* __restrict__ p1,
                                              uint32_t* __restrict__ p2) {
    size_t i = (size_t)blockIdx.x * 256 + threadIdx.x;
    float2 v = x[i];
    uint32_t a, b;
    splitp(v.x, v.y, a, b);
    p1[i] = a; p2[i] = b;
}

// all 6 weights: W[k][n] -> T[n][k], B-side scaled planes:
// B1s = fp16(63b/64), e1 = 63b/64 - B1s, B2s = fp16(b/64 + e1)
__global__ void __launch_bounds__(256)
wsplit_all(const float* __restrict__ wq, const float* __restrict__ mlp_w,
           const float* __restrict__ w_out,
           __half* __restrict__ T1, __half* __restrict__ T2) {
    __shared__ float t[32][33];
    const int z = blockIdx.z;
    const float* W = (z == 0) ? wq : (z <= 4 ? mlp_w + (size_t)(z - 1) * DD : w_out);
    __half* t1 = T1 + (size_t)z * DD;
    __half* t2 = T2 + (size_t)z * DD;
    const int bx = blockIdx.x * 32, by = blockIdx.y * 32;
    const int tx = threadIdx.x, ty = threadIdx.y;
#pragma unroll
    for (int i = 0; i < 32; i += 8) t[ty + i][tx] = W[(size_t)(by + ty + i) * D + bx + tx];
    __syncthreads();
#pragma unroll
    for (int i = 0; i < 32; i += 8) {
        float b = t[tx][ty + i];
        float bmain = b * (63.0f / 64.0f);
        __half h1 = __float2half_rn(bmain);
        float e1 = bmain - __half2float(h1);
        __half h2 = __float2half_rn(b * (1.0f / 64.0f) + e1);
        size_t o = (size_t)(bx + ty + i) * D + by + tx;
        t1[o] = h1;
        t2[o] = h2;
    }
}

// LayerNorm (D=1024, eps=1e-5, no affine) fused with plane-pair output
__global__ void __launch_bounds__(256) ln_split(const float* __restrict__ in,
                                                uint32_t* __restrict__ p1,
                                                uint32_t* __restrict__ p2) {
    __shared__ float2 red[8];
    const int row = blockIdx.x;
    const int tid = threadIdx.x;
    const float4 v = *(const float4*)(in + (size_t)row * D + tid * 4);
    float s = v.x + v.y + v.z + v.w;
    float ss = v.x * v.x + v.y * v.y + v.z * v.z + v.w * v.w;
#pragma unroll
    for (int o = 16; o > 0; o >>= 1) {
        s += __shfl_xor_sync(0xFFFFFFFFu, s, o);
        ss += __shfl_xor_sync(0xFFFFFFFFu, ss, o);
    }
    if ((tid & 31) == 0) red[tid >> 5] = make_float2(s, ss);
    __syncthreads();
    if (tid < 32) {
        float2 r0 = (tid < 8) ? red[tid] : make_float2(0.f, 0.f);
        s = r0.x; ss = r0.y;
#pragma unroll
        for (int o = 4; o > 0; o >>= 1) {
            s += __shfl_xor_sync(0xFFFFFFFFu, s, o);
            ss += __shfl_xor_sync(0xFFFFFFFFu, ss, o);
        }
        if (tid == 0) red[0] = make_float2(s, ss);
    }
    __syncthreads();
    const float mu = red[0].x * (1.0f / D);
    const float var = red[0].y * (1.0f / D) - mu * mu;
    const float r = rsqrtf(var + 1e-5f);
    uint2 h1, h2;
    splitp((v.x - mu) * r, (v.y - mu) * r, h1.x, h2.x);
    splitp((v.z - mu) * r, (v.w - mu) * r, h1.y, h2.y);
    *(uint2*)&p1[(size_t)row * (D / 2) + tid * 2] = h1;
    *(uint2*)&p2[(size_t)row * (D / 2) + tid * 2] = h2;
}

// ---------------- launch ----------------
extern "C" void kernel_launch(void* const* d_in, const int* in_sizes, int n_in,
                              void* d_out, int out_size) {
    const float* x     = (const float*)d_in[0];
    const float* wq    = (const float*)d_in[1];
    const float* bq    = (const float*)d_in[2];
    const float* mlp_w = (const float*)d_in[3];
    const float* mlp_b = (const float*)d_in[4];
    const float* w_out = (const float*)d_in[5];
    const float* b_out = (const float*)d_in[6];
    float* out = (float*)d_out;
    const int M = in_sizes[0] / D;   // 16384

    __half *a1, *a2, *c1, *c2, *w1, *w2;
    float* q;
    cudaGetSymbolAddress((void**)&a1, g_a1);
    cudaGetSymbolAddress((void**)&a2, g_a2);
    cudaGetSymbolAddress((void**)&c1, g_c1);
    cudaGetSymbolAddress((void**)&c2, g_c2);
    cudaGetSymbolAddress((void**)&w1, g_w1);
    cudaGetSymbolAddress((void**)&w2, g_w2);
    cudaGetSymbolAddress((void**)&q, g_q);

    cudaFuncSetAttribute(gemm_hmma<0, 1>, cudaFuncAttributeMaxDynamicSharedMemorySize, SMEM_SZ);
    cudaFuncSetAttribute(gemm_hmma<1, 0>, cudaFuncAttributeMaxDynamicSharedMemorySize, SMEM_SZ);
    cudaFuncSetAttribute(gemm_hmma<0, 0>, cudaFuncAttributeMaxDynamicSharedMemorySize, SMEM_SZ);

    dim3 wg(D / 32, D / 32, 6), wb(32, 8);
    wsplit_all<<<wg, wb>>>(wq, mlp_w, w_out, w1, w2);

    xsplit<<<(M * D) / 512, 256>>>((const float2*)x, (uint32_t*)a1, (uint32_t*)a2);

    dim3 gg(D / 128, M / 128), bb(256);
    // q = x @ wq + bq (fp32 out)
    gemm_hmma<0, 1><<<gg, bb, SMEM_SZ>>>(a1, a2, w1, w2, bq, nullptr, nullptr, q);
    // q_norm = LN(q) -> plane pair
    ln_split<<<M, 256>>>(q, (uint32_t*)c1, (uint32_t*)c2);
    // memory MLP: 3x (GEMM+SiLU), final GEMM no act
    gemm_hmma<1, 0><<<gg, bb, SMEM_SZ>>>(c1, c2, w1 + 1ull * DD, w2 + 1ull * DD, mlp_b + 0 * D, a1, a2, nullptr);
    gemm_hmma<1, 0><<<gg, bb, SMEM_SZ>>>(a1, a2, w1 + 2ull * DD, w2 + 2ull * DD, mlp_b + 1 * D, c1, c2, nullptr);
    gemm_hmma<1, 0><<<gg, bb, SMEM_SZ>>>(c1, c2, w1 + 3ull * DD, w2 + 3ull * DD, mlp_b + 2 * D, a1, a2, nullptr);
    gemm_hmma<0, 0><<<gg, bb, SMEM_SZ>>>(a1, a2, w1 + 4ull * DD, w2 + 4ull * DD, mlp_b + 3 * D, c1, c2, nullptr);
    // out = h @ w_out + b_out (straight-through term is 0 in forward)
    gemm_hmma<0, 1><<<gg, bb, SMEM_SZ>>>(c1, c2, w1 + 5ull * DD, w2 + 5ull * DD, b_out, nullptr, nullptr, out);
}